// round 15
// baseline (speedup 1.0000x reference)
#include <cuda_runtime.h>
#include <math.h>

#define NROW 512
#define CZ   128
#define NPAIR (NROW * NROW) /* 262144 */

typedef unsigned int u32;

// ---------------- device scratch ----------------
__device__ float g_A[(size_t)CZ * NPAIR];   // a, [c][i*512 + k] natural
__device__ float g_B[(size_t)CZ * NPAIR];   // b, [c][j*512 + k] natural
__device__ float g_G[(size_t)NPAIR * CZ];   // gate, [pair][cz]
__device__ float g_T[(size_t)CZ * NPAIR];   // t, [c][i*512+j]
__device__ float g_wt[6 * 128 * 128];       // weights transposed [n][k] natural
// img order: 0 w_ap, 1 w_ag, 2 w_bp, 3 w_bg, 4 w_g, 5 w_z

// ---------------- helpers ----------------
__device__ __forceinline__ float tf32r(float x) {
    float r;
    asm("cvt.rna.tf32.f32 %0, %1;" : "=f"(r) : "f"(x));
    return r;
}
__device__ __forceinline__ float wsum(float v) {
#pragma unroll
    for (int o = 16; o; o >>= 1) v += __shfl_xor_sync(0xffffffffu, v, o);
    return v;
}
__device__ __forceinline__ float sigm(float x) {
    return 1.0f / (1.0f + __expf(-x));
}
__device__ __forceinline__ void mma8(float* d, const u32* a, const u32* b) {
    asm volatile(
        "mma.sync.aligned.m16n8k8.row.col.f32.tf32.tf32.f32 "
        "{%0,%1,%2,%3}, {%4,%5,%6,%7}, {%8,%9}, {%0,%1,%2,%3};"
        : "+f"(d[0]), "+f"(d[1]), "+f"(d[2]), "+f"(d[3])
        : "r"(a[0]), "r"(a[1]), "r"(a[2]), "r"(a[3]), "r"(b[0]), "r"(b[1]));
}
__device__ __forceinline__ u32 smem_u32(const void* p) {
    u32 a;
    asm("{ .reg .u64 t; cvta.to.shared.u64 t, %1; cvt.u32.u64 %0, t; }" : "=r"(a) : "l"(p));
    return a;
}
__device__ __forceinline__ void cpa16(u32 dst, const void* src) {
    asm volatile("cp.async.cg.shared.global [%0], [%1], 16;" :: "r"(dst), "l"(src));
}
#define CP_COMMIT() asm volatile("cp.async.commit_group;" ::: "memory")
#define CP_WAIT(n)  asm volatile("cp.async.wait_group %0;" :: "n"(n) : "memory")

// ldmatrix x4: one 16x8-f32 A fragment (a0..a3) OR two n8k8 B fragments.
#define LDSM4(R, ADDR) \
    asm volatile("ldmatrix.sync.aligned.m8n8.x4.shared.b16 {%0,%1,%2,%3}, [%4];" \
        : "=r"((R)[0]), "=r"((R)[1]), "=r"((R)[2]), "=r"((R)[3]) : "r"(ADDR))

// LDSM lane roles
#define ROWA(lane) ((lane) & 15)
#define KHA(lane)  ((lane) >> 4)
#define ROWB(lane) (((lane) & 7) | (((lane) >> 4) << 3))
#define KHB(lane)  (((lane) >> 3) & 1)

// ============================================================================
// prep: transpose + tf32-round weights into natural [n][k] layout
// ============================================================================
__global__ void prep_w(const float* __restrict__ wap, const float* __restrict__ wag,
                       const float* __restrict__ wbp, const float* __restrict__ wbg,
                       const float* __restrict__ wg,  const float* __restrict__ wz) {
    int img = blockIdx.y;
    int lin = blockIdx.x * 256 + threadIdx.x;
    int n = lin >> 7, k = lin & 127;
    const float* s;
    switch (img) {
        case 0: s = wap; break; case 1: s = wag; break;
        case 2: s = wbp; break; case 3: s = wbg; break;
        case 4: s = wg;  break; default: s = wz; break;
    }
    g_wt[img * 16384 + lin] = tf32r(s[k * 128 + n]);
}

// load a 64-row weight chunk into Wc, row stride 132 floats (33 f4)
__device__ __forceinline__ void loadWc132(float* __restrict__ Wc, int img, int nb, int tid) {
    const float4* src = (const float4*)(g_wt + img * 16384);
#pragma unroll
    for (int it = 0; it < 8; ++it) {
        int lin = it * 256 + tid;
        int row = lin >> 5, q = lin & 31;
        ((float4*)Wc)[row * 33 + q] = src[(nb + row) * 32 + q];
    }
}

// ============================================================================
// GEMM: warp tile m16 x n32, K=128, LDSM fragments. acc[4][4].
// ============================================================================
__device__ __forceinline__ void gemm16x32(u32 asb, u32 wcb, float acc[4][4]) {
#pragma unroll
    for (int i = 0; i < 4; ++i)
#pragma unroll
        for (int q = 0; q < 4; ++q) acc[i][q] = 0.f;
#pragma unroll
    for (int ks = 0; ks < 16; ++ks) {
        u32 a[4], b0[4], b1[4];
        LDSM4(a, asb + ks * 32);
        LDSM4(b0, wcb + ks * 32);
        LDSM4(b1, wcb + 16 * 132 * 4 + ks * 32);
        mma8(acc[0], a, b0);  mma8(acc[1], a, b0 + 2);
        mma8(acc[2], a, b1);  mma8(acc[3], a, b1 + 2);
    }
}

// ============================================================================
// proj_all: FUSED. 64-pair tiles, warp tile m16n32, LN once, then
// ap||ag -> g_A, bp||bg -> g_B, g -> g_G. All natural layouts.
// smem = As(64x132)+Wc(64x132) = 67584B -> 3 CTAs/SM.
// ============================================================================
__global__ __launch_bounds__(256, 3) void proj_all_kernel(
    const float* __restrict__ z,
    const float* __restrict__ lnw, const float* __restrict__ lnb,
    const float* __restrict__ b_ap, const float* __restrict__ b_ag,
    const float* __restrict__ b_bp, const float* __restrict__ b_bg,
    const float* __restrict__ b_g)
{
    extern __shared__ float smf[];
    float* As = smf;                 // 64 x 132
    float* Wc = smf + 64 * 132;      // 64 x 132
    const int tid = threadIdx.x;
    const int wid = tid >> 5, lane = tid & 31;
    const int g = lane >> 2, t = lane & 3;
    const int m0 = (wid & 3) * 16, n0 = (wid >> 2) * 32;
    const size_t pair0 = (size_t)blockIdx.x * 64;

    // ---- LN -> As (natural k order); warp handles 8 rows ----
    {
        float4 lw = ((const float4*)lnw)[lane];
        float4 lb = ((const float4*)lnb)[lane];
#pragma unroll 2
        for (int r = 0; r < 8; ++r) {
            int row = wid * 8 + r;
            float4 x = ((const float4*)(z + (pair0 + row) * (size_t)CZ))[lane];
            float m = wsum(x.x + x.y + x.z + x.w) * (1.0f / 128.0f);
            float dx = x.x - m, dy = x.y - m, dz = x.z - m, dw = x.w - m;
            float var = wsum(dx * dx + dy * dy + dz * dz + dw * dw) * (1.0f / 128.0f);
            float rs = rsqrtf(var + 1e-5f);
            float4 o;
            o.x = tf32r(dx * rs * lw.x + lb.x);
            o.y = tf32r(dy * rs * lw.y + lb.y);
            o.z = tf32r(dz * rs * lw.z + lb.z);
            o.w = tf32r(dw * rs * lw.w + lb.w);
            *(float4*)(As + row * 132 + lane * 4) = o;
        }
    }

    const u32 asb = smem_u32(As) + (u32)((m0 + ROWA(lane)) * 132 + KHA(lane) * 4) * 4u;
    const u32 wcb = smem_u32(Wc) + (u32)((ROWB(lane) + n0) * 132 + KHB(lane) * 4) * 4u;
    const int r = m0 + g;

    float accg[4][4], accp[4][4];

    // ---- a then b ----
#pragma unroll 1
    for (int sel = 0; sel < 2; ++sel) {
        const int imgP = sel * 2, imgG = sel * 2 + 1;
        const float* bp = sel ? b_bp : b_ap;
        const float* bg = sel ? b_bg : b_ag;
        float* __restrict__ dst = sel ? g_B : g_A;
#pragma unroll 1
        for (int cb = 0; cb < 128; cb += 64) {
            __syncthreads();
            loadWc132(Wc, imgG, cb, tid);
            __syncthreads();
            gemm16x32(asb, wcb, accg);
            __syncthreads();
            loadWc132(Wc, imgP, cb, tid);
            __syncthreads();
            gemm16x32(asb, wcb, accp);
#pragma unroll
            for (int nt = 0; nt < 4; ++nt) {
                int c = cb + n0 + nt * 8 + 2 * t;
                float2 bpv = *(const float2*)(bp + c);
                float2 bgv = *(const float2*)(bg + c);
                float* d0 = dst + (size_t)c * NPAIR + pair0;
                float* d1 = dst + (size_t)(c + 1) * NPAIR + pair0;
                const float* P = accp[nt];
                const float* G = accg[nt];
                d0[r]     = tf32r(sigm(G[0] + bgv.x) * (P[0] + bpv.x));
                d1[r]     = tf32r(sigm(G[1] + bgv.y) * (P[1] + bpv.y));
                d0[r + 8] = tf32r(sigm(G[2] + bgv.x) * (P[2] + bpv.x));
                d1[r + 8] = tf32r(sigm(G[3] + bgv.y) * (P[3] + bpv.y));
            }
        }
    }

    // ---- gate g (natural rows, float2 stores) ----
#pragma unroll 1
    for (int cb = 0; cb < 128; cb += 64) {
        __syncthreads();
        loadWc132(Wc, 4, cb, tid);
        __syncthreads();
        gemm16x32(asb, wcb, accg);
#pragma unroll
        for (int nt = 0; nt < 4; ++nt) {
            int c = cb + n0 + nt * 8 + 2 * t;
            float2 bgv = *(const float2*)(b_g + c);
            const float* G = accg[nt];
            *(float2*)(g_G + (pair0 + r) * (size_t)CZ + c) =
                make_float2(sigm(G[0] + bgv.x), sigm(G[1] + bgv.y));
            *(float2*)(g_G + (pair0 + r + 8) * (size_t)CZ + c) =
                make_float2(sigm(G[2] + bgv.x), sigm(G[3] + bgv.y));
        }
    }
}

// ============================================================================
// tri: t[c][i][j] = sum_k a[c][i][k]*b[c][j][k]; 128x128 tile, K chunks of 32,
// cp.async double-buffered, LDSM fragments. Buffers: A/B 128 rows x 36 stride.
// smem = 4 x 18432 = 73728B -> 2 CTAs/SM.
// ============================================================================
__global__ __launch_bounds__(256, 2) void tri_kernel()
{
    extern __shared__ float smf[];   // [A0 4608f | B0 4608f | A1 | B1]
    const int tid = threadIdx.x;
    const int wid = tid >> 5, lane = tid & 31;
    const int g = lane >> 2, t = lane & 3;
    const int m0 = (wid & 3) * 32, n0 = (wid >> 2) * 64;
    const int c  = blockIdx.z;
    const int i0 = blockIdx.y * 128;
    const int j0 = blockIdx.x * 128;
    const float* __restrict__ asrc = g_A + (size_t)c * NPAIR + (size_t)i0 * NROW;
    const float* __restrict__ bsrc = g_B + (size_t)c * NPAIR + (size_t)j0 * NROW;
    const u32 smb = smem_u32(smf);

    int offg[4];
    u32 offs[4];
#pragma unroll
    for (int it = 0; it < 4; ++it) {
        int lin = it * 256 + tid, row = lin >> 3, j = lin & 7;
        offg[it] = row * NROW + j * 4;
        offs[it] = (u32)(row * 36 + j * 4) * 4u;
    }
    const u32 bufA0 = smb;
    const u32 bufB0 = smb + 4608u * 4u;
    const u32 bufA1 = smb + 9216u * 4u;
    const u32 bufB1 = smb + 13824u * 4u;

    float acc[2][8][4];
#pragma unroll
    for (int i = 0; i < 2; ++i)
#pragma unroll
        for (int j = 0; j < 8; ++j)
#pragma unroll
            for (int q = 0; q < 4; ++q) acc[i][j][q] = 0.f;

    const u32 aofs = (u32)((m0 + ROWA(lane)) * 36 + KHA(lane) * 4) * 4u;
    const u32 bofs = (u32)((n0 + ROWB(lane)) * 36 + KHB(lane) * 4) * 4u;

    auto issue2 = [&](u32 baseA, u32 baseB, int k0) {
#pragma unroll
        for (int it = 0; it < 4; ++it) {
            cpa16(baseA + offs[it], asrc + offg[it] + k0);
            cpa16(baseB + offs[it], bsrc + offg[it] + k0);
        }
    };

    auto compute = [&](u32 baseA, u32 baseB) {
#pragma unroll
        for (int ks = 0; ks < 4; ++ks) {
            u32 a0[4], a1[4];
            LDSM4(a0, baseA + aofs + ks * 32);
            LDSM4(a1, baseA + aofs + 16 * 36 * 4 + ks * 32);
#pragma unroll
            for (int s = 0; s < 4; ++s) {
                u32 b[4];
                LDSM4(b, baseB + bofs + (u32)(s * 16 * 36 * 4) + ks * 32);
                mma8(acc[0][s * 2],     a0, b);
                mma8(acc[0][s * 2 + 1], a0, b + 2);
                mma8(acc[1][s * 2],     a1, b);
                mma8(acc[1][s * 2 + 1], a1, b + 2);
            }
        }
    };

    issue2(bufA0, bufB0, 0); CP_COMMIT();

#pragma unroll 1
    for (int kc2 = 0; kc2 < 8; ++kc2) {
        const int kc = kc2 * 2;
        issue2(bufA1, bufB1, (kc + 1) * 32); CP_COMMIT(); CP_WAIT(1);
        __syncthreads();
        compute(bufA0, bufB0);
        __syncthreads();
        if (kc + 2 < 16) { issue2(bufA0, bufB0, (kc + 2) * 32); CP_COMMIT(); CP_WAIT(1); }
        else             { CP_WAIT(0); }
        __syncthreads();
        compute(bufA1, bufB1);
        __syncthreads();
    }

    float* __restrict__ tdst = g_T + (size_t)c * NPAIR;
#pragma unroll
    for (int mt = 0; mt < 2; ++mt) {
        int r = i0 + m0 + mt * 16 + g;
#pragma unroll
        for (int nt = 0; nt < 8; ++nt) {
            int cl = j0 + n0 + nt * 8 + 2 * t;
            *(float2*)(tdst + (size_t)r * NROW + cl) =
                make_float2(acc[mt][nt][0], acc[mt][nt][1]);
            *(float2*)(tdst + (size_t)(r + 8) * NROW + cl) =
                make_float2(acc[mt][nt][2], acc[mt][nt][3]);
        }
    }
}

// ============================================================================
// final: out[pair][cz] = g * (LN_c(t) @ Wz + bz). 64-pair tiles, grid 4096.
// Natural-layout Wc (stride 132), B fragments via TWO scalar LDS
// (bank = (4g+t) mod 32 -> conflict-free).
// smem = As(128x72) + Wc(64x132) + stats = 73216B -> 3 CTAs/SM.
// ============================================================================
__global__ __launch_bounds__(256, 3) void final_kernel(
    const float* __restrict__ lnw, const float* __restrict__ lnb,
    const float* __restrict__ bz, float* __restrict__ out)
{
    extern __shared__ float smf[];
    float* As = smf;                 // [128 c][72 pair] k-major
    float* Wc = As + 128 * 72;       // 64 x 132 (natural)
    float* PS = Wc + 64 * 132;       // 256
    float* PQ = PS + 256;            // 256
    float* MS = PQ + 256;            // 64
    float* RS = MS + 64;             // 64
    const int tid = threadIdx.x;
    const int wid = tid >> 5, lane = tid & 31;
    const int g = lane >> 2, t = lane & 3;
    const int m0 = (wid & 3) * 16, n0 = (wid >> 2) * 32;
    const int p = tid & 63, ch = tid >> 6;
    const size_t pair0 = (size_t)blockIdx.x * 64;
    const u32 smb = smem_u32(smf);

    // ---- async gather of t: 2048 x 16B ----
#pragma unroll
    for (int it = 0; it < 8; ++it) {
        int lin = it * 256 + tid;
        int c = lin >> 4, p4 = lin & 15;
        cpa16(smb + (u32)(c * 72 + p4 * 4) * 4u,
              g_T + (size_t)c * NPAIR + pair0 + p4 * 4);
    }
    CP_COMMIT();
    CP_WAIT(0);
    __syncthreads();

    // ---- stats from smem ----
    {
        float s = 0.f, qq = 0.f;
#pragma unroll 4
        for (int cc = 0; cc < 32; ++cc) {
            int c = ch * 32 + cc;
            float v = As[c * 72 + p];
            s += v; qq += v * v;
        }
        PS[tid] = s; PQ[tid] = qq;
    }
    __syncthreads();
    if (tid < 64) {
        float ss = PS[tid] + PS[tid + 64] + PS[tid + 128] + PS[tid + 192];
        float sq = PQ[tid] + PQ[tid + 64] + PQ[tid + 128] + PQ[tid + 192];
        float m = ss * (1.0f / 128.0f);
        MS[tid] = m;
        RS[tid] = rsqrtf(fmaxf(sq * (1.0f / 128.0f) - m * m, 0.f) + 1e-5f);
    }
    __syncthreads();

    // normalize in place
    {
        float mp = MS[p], rp = RS[p];
#pragma unroll 4
        for (int cc = 0; cc < 32; ++cc) {
            int c = ch * 32 + cc;
            float lw = __ldg(lnw + c), lb = __ldg(lnb + c);
            As[c * 72 + p] = tf32r((As[c * 72 + p] - mp) * rp * lw + lb);
        }
    }

    const int r = m0 + g;

#pragma unroll 1
    for (int cb = 0; cb < 128; cb += 64) {
        __syncthreads();
        loadWc132(Wc, 5, cb, tid);
        __syncthreads();

        float acc[4][4];
#pragma unroll
        for (int i = 0; i < 4; ++i)
#pragma unroll
            for (int q = 0; q < 4; ++q) acc[i][q] = 0.f;

#pragma unroll
        for (int ks = 0; ks < 16; ++ks) {
            const int k0 = ks * 8;
            const float* ap = As + (k0 + t) * 72 + m0 + g;
            u32 aa[4] = { __float_as_uint(ap[0]),      __float_as_uint(ap[8]),
                          __float_as_uint(ap[4 * 72]), __float_as_uint(ap[4 * 72 + 8]) };
#pragma unroll
            for (int nt = 0; nt < 4; ++nt) {
                const float* wrow = Wc + (n0 + nt * 8 + g) * 132 + k0 + t;
                u32 bb[2] = { __float_as_uint(wrow[0]), __float_as_uint(wrow[4]) };
                mma8(acc[nt], aa, bb);
            }
        }

#pragma unroll
        for (int nt = 0; nt < 4; ++nt) {
            int c = cb + n0 + nt * 8 + 2 * t;
            float2 bzv = *(const float2*)(bz + c);
            float2 gv0 = *(const float2*)(g_G + (pair0 + r) * (size_t)CZ + c);
            float2 gv1 = *(const float2*)(g_G + (pair0 + r + 8) * (size_t)CZ + c);
            *(float2*)(out + (pair0 + r) * (size_t)CZ + c) =
                make_float2(gv0.x * (acc[nt][0] + bzv.x), gv0.y * (acc[nt][1] + bzv.y));
            *(float2*)(out + (pair0 + r + 8) * (size_t)CZ + c) =
                make_float2(gv1.x * (acc[nt][2] + bzv.x), gv1.y * (acc[nt][3] + bzv.y));
        }
    }
}

// ============================================================================
// kernel_launch — sequential, single stream
// ============================================================================
extern "C" void kernel_launch(void* const* d_in, const int* in_sizes, int n_in,
                              void* d_out, int out_size)
{
    const float* z        = (const float*)d_in[0];
    const float* ln_in_w  = (const float*)d_in[1];
    const float* ln_in_b  = (const float*)d_in[2];
    const float* ln_out_w = (const float*)d_in[3];
    const float* ln_out_b = (const float*)d_in[4];
    const float* w_ap     = (const float*)d_in[5];
    const float* b_ap     = (const float*)d_in[6];
    const float* w_ag     = (const float*)d_in[7];
    const float* b_ag     = (const float*)d_in[8];
    const float* w_bp     = (const float*)d_in[9];
    const float* b_bp     = (const float*)d_in[10];
    const float* w_bg     = (const float*)d_in[11];
    const float* b_bg     = (const float*)d_in[12];
    const float* w_g      = (const float*)d_in[13];
    const float* b_g      = (const float*)d_in[14];
    const float* w_z      = (const float*)d_in[15];
    const float* b_z      = (const float*)d_in[16];
    float* out = (float*)d_out;

    const int PROJ_SMEM = 2 * 64 * 132 * 4;                    // 67584
    const int TRI_SMEM  = 4 * 4608 * 4;                        // 73728
    const int FIN_SMEM  = (128 * 72 + 64 * 132 + 640) * 4;     // 73216

    cudaFuncSetAttribute(proj_all_kernel, cudaFuncAttributeMaxDynamicSharedMemorySize, PROJ_SMEM);
    cudaFuncSetAttribute(tri_kernel,      cudaFuncAttributeMaxDynamicSharedMemorySize, TRI_SMEM);
    cudaFuncSetAttribute(final_kernel,    cudaFuncAttributeMaxDynamicSharedMemorySize, FIN_SMEM);

    dim3 pgrid(64, 6);
    prep_w<<<pgrid, 256>>>(w_ap, w_ag, w_bp, w_bg, w_g, w_z);

    proj_all_kernel<<<NPAIR / 64, 256, PROJ_SMEM>>>(
        z, ln_in_w, ln_in_b, b_ap, b_ag, b_bp, b_bg, b_g);

    dim3 tgrid(4, 4, 128);
    tri_kernel<<<tgrid, 256, TRI_SMEM>>>();

    final_kernel<<<NPAIR / 64, 256, FIN_SMEM>>>(ln_out_w, ln_out_b, b_z, out);
}

// round 16
// speedup vs baseline: 1.1350x; 1.1350x over previous
#include <cuda_runtime.h>
#include <math.h>

#define NROW 512
#define CZ   128
#define NPAIR (NROW * NROW) /* 262144 */

typedef unsigned int u32;

// ---------------- device scratch ----------------
__device__ float g_A[(size_t)CZ * NPAIR];   // a, [c][i*512 + k] natural
__device__ float g_B[(size_t)CZ * NPAIR];   // b, [c][j*512 + k] natural
__device__ float g_G[(size_t)NPAIR * CZ];   // gate, [pair][cz]
__device__ float g_T[(size_t)CZ * NPAIR];   // t, [c][i*512+j]
__device__ float g_wt[6 * 128 * 128];       // weights transposed [n][k] natural
// img order: 0 w_ap, 1 w_ag, 2 w_bp, 3 w_bg, 4 w_g, 5 w_z

// ---------------- helpers ----------------
__device__ __forceinline__ float tf32r(float x) {
    float r;
    asm("cvt.rna.tf32.f32 %0, %1;" : "=f"(r) : "f"(x));
    return r;
}
__device__ __forceinline__ float wsum(float v) {
#pragma unroll
    for (int o = 16; o; o >>= 1) v += __shfl_xor_sync(0xffffffffu, v, o);
    return v;
}
__device__ __forceinline__ float sigm(float x) {
    return 1.0f / (1.0f + __expf(-x));
}
__device__ __forceinline__ void mma8(float* d, const u32* a, const u32* b) {
    asm volatile(
        "mma.sync.aligned.m16n8k8.row.col.f32.tf32.tf32.f32 "
        "{%0,%1,%2,%3}, {%4,%5,%6,%7}, {%8,%9}, {%0,%1,%2,%3};"
        : "+f"(d[0]), "+f"(d[1]), "+f"(d[2]), "+f"(d[3])
        : "r"(a[0]), "r"(a[1]), "r"(a[2]), "r"(a[3]), "r"(b[0]), "r"(b[1]));
}
__device__ __forceinline__ u32 smem_u32(const void* p) {
    u32 a;
    asm("{ .reg .u64 t; cvta.to.shared.u64 t, %1; cvt.u32.u64 %0, t; }" : "=r"(a) : "l"(p));
    return a;
}
__device__ __forceinline__ void cpa16(u32 dst, const void* src) {
    asm volatile("cp.async.cg.shared.global [%0], [%1], 16;" :: "r"(dst), "l"(src));
}
#define CP_COMMIT() asm volatile("cp.async.commit_group;" ::: "memory")
#define CP_WAIT(n)  asm volatile("cp.async.wait_group %0;" :: "n"(n) : "memory")

// ldmatrix x4: one 16x8-f32 A fragment (a0..a3) OR two n8k8 B fragments.
#define LDSM4(R, ADDR) \
    asm volatile("ldmatrix.sync.aligned.m8n8.x4.shared.b16 {%0,%1,%2,%3}, [%4];" \
        : "=r"((R)[0]), "=r"((R)[1]), "=r"((R)[2]), "=r"((R)[3]) : "r"(ADDR))

// LDSM lane roles
#define ROWA(lane) ((lane) & 15)
#define KHA(lane)  ((lane) >> 4)
#define ROWB(lane) (((lane) & 7) | (((lane) >> 4) << 3))
#define KHB(lane)  (((lane) >> 3) & 1)

// ============================================================================
// prep: transpose + tf32-round weights into natural [n][k] layout
// ============================================================================
__global__ void prep_w(const float* __restrict__ wap, const float* __restrict__ wag,
                       const float* __restrict__ wbp, const float* __restrict__ wbg,
                       const float* __restrict__ wg,  const float* __restrict__ wz) {
    int img = blockIdx.y;
    int lin = blockIdx.x * 256 + threadIdx.x;
    int n = lin >> 7, k = lin & 127;
    const float* s;
    switch (img) {
        case 0: s = wap; break; case 1: s = wag; break;
        case 2: s = wbp; break; case 3: s = wbg; break;
        case 4: s = wg;  break; default: s = wz; break;
    }
    g_wt[img * 16384 + lin] = tf32r(s[k * 128 + n]);
}

// async load of a 64-row weight chunk into Wc (row stride 132 floats = 528 B)
__device__ __forceinline__ void loadWc_async(u32 wcbase, int img, int nb, int tid) {
    const float4* src = (const float4*)(g_wt + img * 16384);
#pragma unroll
    for (int it = 0; it < 8; ++it) {
        int lin = it * 256 + tid;          // 0..2047
        int row = lin >> 5, q = lin & 31;
        cpa16(wcbase + (u32)(row * 33 + q) * 16u, src + (nb + row) * 32 + q);
    }
    CP_COMMIT();
}

// ============================================================================
// GEMM: warp tile m32 x n32, K=128, LDSM fragments.
// As (128 rows x 132 stride), Wc (64 rows x 132 stride). acc[2][4][4].
// ============================================================================
__device__ __forceinline__ void gemm32x32(u32 asb, u32 wcb, float acc[2][4][4]) {
#pragma unroll
    for (int m = 0; m < 2; ++m)
#pragma unroll
        for (int i = 0; i < 4; ++i)
#pragma unroll
            for (int q = 0; q < 4; ++q) acc[m][i][q] = 0.f;
#pragma unroll
    for (int ks = 0; ks < 16; ++ks) {
        u32 a0[4], a1[4], b0[4], b1[4];
        LDSM4(a0, asb + ks * 32);
        LDSM4(a1, asb + 16 * 132 * 4 + ks * 32);
        LDSM4(b0, wcb + ks * 32);
        LDSM4(b1, wcb + 16 * 132 * 4 + ks * 32);
        mma8(acc[0][0], a0, b0);     mma8(acc[0][1], a0, b0 + 2);
        mma8(acc[0][2], a0, b1);     mma8(acc[0][3], a0, b1 + 2);
        mma8(acc[1][0], a1, b0);     mma8(acc[1][1], a1, b0 + 2);
        mma8(acc[1][2], a1, b1);     mma8(acc[1][3], a1, b1 + 2);
    }
}

// ============================================================================
// proj_all: FUSED (R13 shape). 128-pair tiles, warp tile m32n32, LN once,
// then ap||ag -> g_A, bp||bg -> g_B, g -> g_G. cp.async weight staging.
// smem = As(128x132)+Wc(64x132) = 101376B -> 2 CTAs/SM.
// ============================================================================
__global__ __launch_bounds__(256, 2) void proj_all_kernel(
    const float* __restrict__ z,
    const float* __restrict__ lnw, const float* __restrict__ lnb,
    const float* __restrict__ b_ap, const float* __restrict__ b_ag,
    const float* __restrict__ b_bp, const float* __restrict__ b_bg,
    const float* __restrict__ b_g)
{
    extern __shared__ float smf[];
    float* As = smf;                 // 128 x 132
    float* Wc = smf + 128 * 132;     // 64 x 132
    const int tid = threadIdx.x;
    const int wid = tid >> 5, lane = tid & 31;
    const int g = lane >> 2, t = lane & 3;
    const int m0 = (wid & 3) * 32, n0 = (wid >> 2) * 32;
    const size_t pair0 = (size_t)blockIdx.x * 128;
    const u32 wcbase = smem_u32(Wc);

    // prefetch first weight chunk while doing LN
    loadWc_async(wcbase, 1, 0, tid);   // w_ag chunk 0

    // ---- LN -> As (natural k order) ----
    {
        float4 lw = ((const float4*)lnw)[lane];
        float4 lb = ((const float4*)lnb)[lane];
#pragma unroll 2
        for (int r = 0; r < 16; ++r) {
            int row = wid * 16 + r;
            float4 x = ((const float4*)(z + (pair0 + row) * (size_t)CZ))[lane];
            float m = wsum(x.x + x.y + x.z + x.w) * (1.0f / 128.0f);
            float dx = x.x - m, dy = x.y - m, dz = x.z - m, dw = x.w - m;
            float var = wsum(dx * dx + dy * dy + dz * dz + dw * dw) * (1.0f / 128.0f);
            float rs = rsqrtf(var + 1e-5f);
            float4 o;
            o.x = tf32r(dx * rs * lw.x + lb.x);
            o.y = tf32r(dy * rs * lw.y + lb.y);
            o.z = tf32r(dz * rs * lw.z + lb.z);
            o.w = tf32r(dw * rs * lw.w + lb.w);
            *(float4*)(As + row * 132 + lane * 4) = o;
        }
    }

    const u32 asb = smem_u32(As) + (u32)((m0 + ROWA(lane)) * 132 + KHA(lane) * 4) * 4u;
    const u32 wcb = wcbase + (u32)((n0 + ROWB(lane)) * 132 + KHB(lane) * 4) * 4u;
    const int r0 = m0 + g, r1 = m0 + 16 + g;

    float accg[2][4][4], accp[2][4][4];

    // ---- a then b ----
#pragma unroll 1
    for (int sel = 0; sel < 2; ++sel) {
        const int imgP = sel * 2, imgG = sel * 2 + 1;
        const float* bp = sel ? b_bp : b_ap;
        const float* bg = sel ? b_bg : b_ag;
        float* __restrict__ dst = sel ? g_B : g_A;
#pragma unroll 1
        for (int cb = 0; cb < 128; cb += 64) {
            // gate weights already in flight (prefetched at tail of prev phase)
            CP_WAIT(0);
            __syncthreads();
            gemm32x32(asb, wcb, accg);
            __syncthreads();
            loadWc_async(wcbase, imgP, cb, tid);
            CP_WAIT(0);
            __syncthreads();
            gemm32x32(asb, wcb, accp);
            __syncthreads();
            // prefetch NEXT phase's gate weights; overlaps with epilogue stores
            {
                int ncb = cb + 64;
                if (ncb < 128)            loadWc_async(wcbase, imgG, ncb, tid);
                else if (sel == 0)        loadWc_async(wcbase, 3, 0, tid);       // w_bg c0
                else                      loadWc_async(wcbase, 4, 0, tid);       // w_g c0
            }
#pragma unroll
            for (int mt = 0; mt < 2; ++mt) {
                const int r = mt ? r1 : r0;
#pragma unroll
                for (int nt = 0; nt < 4; ++nt) {
                    int c = cb + n0 + nt * 8 + 2 * t;
                    float2 bpv = *(const float2*)(bp + c);
                    float2 bgv = *(const float2*)(bg + c);
                    float* d0 = dst + (size_t)c * NPAIR + pair0;
                    float* d1 = dst + (size_t)(c + 1) * NPAIR + pair0;
                    const float* P = accp[mt][nt];
                    const float* G = accg[mt][nt];
                    d0[r]     = tf32r(sigm(G[0] + bgv.x) * (P[0] + bpv.x));
                    d1[r]     = tf32r(sigm(G[1] + bgv.y) * (P[1] + bpv.y));
                    d0[r + 8] = tf32r(sigm(G[2] + bgv.x) * (P[2] + bpv.x));
                    d1[r + 8] = tf32r(sigm(G[3] + bgv.y) * (P[3] + bpv.y));
                }
            }
        }
    }

    // ---- gate g (natural rows, float2 stores) ----
#pragma unroll 1
    for (int cb = 0; cb < 128; cb += 64) {
        CP_WAIT(0);
        __syncthreads();
        gemm32x32(asb, wcb, accg);
        __syncthreads();
        if (cb + 64 < 128) loadWc_async(wcbase, 4, cb + 64, tid);
#pragma unroll
        for (int mt = 0; mt < 2; ++mt) {
            const int r = mt ? r1 : r0;
#pragma unroll
            for (int nt = 0; nt < 4; ++nt) {
                int c = cb + n0 + nt * 8 + 2 * t;
                float2 bgv = *(const float2*)(b_g + c);
                const float* G = accg[mt][nt];
                *(float2*)(g_G + (pair0 + r) * (size_t)CZ + c) =
                    make_float2(sigm(G[0] + bgv.x), sigm(G[1] + bgv.y));
                *(float2*)(g_G + (pair0 + r + 8) * (size_t)CZ + c) =
                    make_float2(sigm(G[2] + bgv.x), sigm(G[3] + bgv.y));
            }
        }
    }
}

// ============================================================================
// tri: t[c][i][j] = sum_k a[c][i][k]*b[c][j][k]; 128x128 tile, K chunks of 32,
// cp.async double-buffered, LDSM fragments. Buffers: A/B 128 rows x 36 stride.
// smem = 4 x 18432 = 73728B -> 2 CTAs/SM.
// ============================================================================
__global__ __launch_bounds__(256, 2) void tri_kernel()
{
    extern __shared__ float smf[];   // [A0 4608f | B0 4608f | A1 | B1]
    const int tid = threadIdx.x;
    const int wid = tid >> 5, lane = tid & 31;
    const int g = lane >> 2, t = lane & 3;
    const int m0 = (wid & 3) * 32, n0 = (wid >> 2) * 64;
    const int c  = blockIdx.z;
    const int i0 = blockIdx.y * 128;
    const int j0 = blockIdx.x * 128;
    const float* __restrict__ asrc = g_A + (size_t)c * NPAIR + (size_t)i0 * NROW;
    const float* __restrict__ bsrc = g_B + (size_t)c * NPAIR + (size_t)j0 * NROW;
    const u32 smb = smem_u32(smf);

    int offg[4];
    u32 offs[4];
#pragma unroll
    for (int it = 0; it < 4; ++it) {
        int lin = it * 256 + tid, row = lin >> 3, j = lin & 7;
        offg[it] = row * NROW + j * 4;
        offs[it] = (u32)(row * 36 + j * 4) * 4u;
    }
    const u32 bufA0 = smb;
    const u32 bufB0 = smb + 4608u * 4u;
    const u32 bufA1 = smb + 9216u * 4u;
    const u32 bufB1 = smb + 13824u * 4u;

    float acc[2][8][4];
#pragma unroll
    for (int i = 0; i < 2; ++i)
#pragma unroll
        for (int j = 0; j < 8; ++j)
#pragma unroll
            for (int q = 0; q < 4; ++q) acc[i][j][q] = 0.f;

    const u32 aofs = (u32)((m0 + ROWA(lane)) * 36 + KHA(lane) * 4) * 4u;
    const u32 bofs = (u32)((n0 + ROWB(lane)) * 36 + KHB(lane) * 4) * 4u;

    auto issue2 = [&](u32 baseA, u32 baseB, int k0) {
#pragma unroll
        for (int it = 0; it < 4; ++it) {
            cpa16(baseA + offs[it], asrc + offg[it] + k0);
            cpa16(baseB + offs[it], bsrc + offg[it] + k0);
        }
    };

    auto compute = [&](u32 baseA, u32 baseB) {
#pragma unroll
        for (int ks = 0; ks < 4; ++ks) {
            u32 a0[4], a1[4];
            LDSM4(a0, baseA + aofs + ks * 32);
            LDSM4(a1, baseA + aofs + 16 * 36 * 4 + ks * 32);
#pragma unroll
            for (int s = 0; s < 4; ++s) {
                u32 b[4];
                LDSM4(b, baseB + bofs + (u32)(s * 16 * 36 * 4) + ks * 32);
                mma8(acc[0][s * 2],     a0, b);
                mma8(acc[0][s * 2 + 1], a0, b + 2);
                mma8(acc[1][s * 2],     a1, b);
                mma8(acc[1][s * 2 + 1], a1, b + 2);
            }
        }
    };

    issue2(bufA0, bufB0, 0); CP_COMMIT();

#pragma unroll 1
    for (int kc2 = 0; kc2 < 8; ++kc2) {
        const int kc = kc2 * 2;
        issue2(bufA1, bufB1, (kc + 1) * 32); CP_COMMIT(); CP_WAIT(1);
        __syncthreads();
        compute(bufA0, bufB0);
        __syncthreads();
        if (kc + 2 < 16) { issue2(bufA0, bufB0, (kc + 2) * 32); CP_COMMIT(); CP_WAIT(1); }
        else             { CP_WAIT(0); }
        __syncthreads();
        compute(bufA1, bufB1);
        __syncthreads();
    }

    float* __restrict__ tdst = g_T + (size_t)c * NPAIR;
#pragma unroll
    for (int mt = 0; mt < 2; ++mt) {
        int r = i0 + m0 + mt * 16 + g;
#pragma unroll
        for (int nt = 0; nt < 8; ++nt) {
            int cl = j0 + n0 + nt * 8 + 2 * t;
            *(float2*)(tdst + (size_t)r * NROW + cl) =
                make_float2(acc[mt][nt][0], acc[mt][nt][1]);
            *(float2*)(tdst + (size_t)(r + 8) * NROW + cl) =
                make_float2(acc[mt][nt][2], acc[mt][nt][3]);
        }
    }
}

// ============================================================================
// final: out[pair][cz] = g * (LN_c(t) @ Wz + bz). 64-pair tiles, grid 4096.
// Natural-layout Wc (stride 132), B fragments via two scalar LDS (conflict-free).
// smem = As(128x72) + Wc(64x132) + stats = 73216B -> 3 CTAs/SM.
// ============================================================================
__global__ __launch_bounds__(256, 3) void final_kernel(
    const float* __restrict__ lnw, const float* __restrict__ lnb,
    const float* __restrict__ bz, float* __restrict__ out)
{
    extern __shared__ float smf[];
    float* As = smf;                 // [128 c][72 pair] k-major
    float* Wc = As + 128 * 72;       // 64 x 132 (natural)
    float* PS = Wc + 64 * 132;       // 256
    float* PQ = PS + 256;            // 256
    float* MS = PQ + 256;            // 64
    float* RS = MS + 64;             // 64
    const int tid = threadIdx.x;
    const int wid = tid >> 5, lane = tid & 31;
    const int g = lane >> 2, t = lane & 3;
    const int m0 = (wid & 3) * 16, n0 = (wid >> 2) * 32;
    const int p = tid & 63, ch = tid >> 6;
    const size_t pair0 = (size_t)blockIdx.x * 64;
    const u32 smb = smem_u32(smf);
    const u32 wcbase = smem_u32(Wc);

    // ---- async gather of t: 2048 x 16B ----
#pragma unroll
    for (int it = 0; it < 8; ++it) {
        int lin = it * 256 + tid;
        int c = lin >> 4, p4 = lin & 15;
        cpa16(smb + (u32)(c * 72 + p4 * 4) * 4u,
              g_T + (size_t)c * NPAIR + pair0 + p4 * 4);
    }
    CP_COMMIT();
    CP_WAIT(0);
    __syncthreads();

    // ---- stats from smem ----
    {
        float s = 0.f, qq = 0.f;
#pragma unroll 4
        for (int cc = 0; cc < 32; ++cc) {
            int c = ch * 32 + cc;
            float v = As[c * 72 + p];
            s += v; qq += v * v;
        }
        PS[tid] = s; PQ[tid] = qq;
    }
    __syncthreads();
    if (tid < 64) {
        float ss = PS[tid] + PS[tid + 64] + PS[tid + 128] + PS[tid + 192];
        float sq = PQ[tid] + PQ[tid + 64] + PQ[tid + 128] + PQ[tid + 192];
        float m = ss * (1.0f / 128.0f);
        MS[tid] = m;
        RS[tid] = rsqrtf(fmaxf(sq * (1.0f / 128.0f) - m * m, 0.f) + 1e-5f);
    }
    __syncthreads();

    // normalize in place
    {
        float mp = MS[p], rp = RS[p];
#pragma unroll 4
        for (int cc = 0; cc < 32; ++cc) {
            int c = ch * 32 + cc;
            float lw = __ldg(lnw + c), lb = __ldg(lnb + c);
            As[c * 72 + p] = tf32r((As[c * 72 + p] - mp) * rp * lw + lb);
        }
    }

    const int r = m0 + g;

#pragma unroll 1
    for (int cb = 0; cb < 128; cb += 64) {
        __syncthreads();
        loadWc_async(wcbase, 5, cb, tid);
        CP_WAIT(0);
        __syncthreads();

        float acc[4][4];
#pragma unroll
        for (int i = 0; i < 4; ++i)
#pragma unroll
            for (int q = 0; q < 4; ++q) acc[i][q] = 0.f;

#pragma unroll
        for (int ks = 0; ks < 16; ++ks) {
            const int k0 = ks * 8;
            const float* ap = As + (k0 + t) * 72 + m0 + g;
            u32 aa[4] = { __float_as_uint(ap[0]),      __float_as_uint(ap[8]),
                          __float_as_uint(ap[4 * 72]), __float_as_uint(ap[4 * 72 + 8]) };
#pragma unroll
            for (int nt = 0; nt < 4; ++nt) {
                const float* wrow = Wc + (n0 + nt * 8 + g) * 132 + k0 + t;
                u32 bb[2] = { __float_as_uint(wrow[0]), __float_as_uint(wrow[4]) };
                mma8(acc[nt], aa, bb);
            }
        }

#pragma unroll
        for (int nt = 0; nt < 4; ++nt) {
            int c = cb + n0 + nt * 8 + 2 * t;
            float2 bzv = *(const float2*)(bz + c);
            float2 gv0 = *(const float2*)(g_G + (pair0 + r) * (size_t)CZ + c);
            float2 gv1 = *(const float2*)(g_G + (pair0 + r + 8) * (size_t)CZ + c);
            *(float2*)(out + (pair0 + r) * (size_t)CZ + c) =
                make_float2(gv0.x * (acc[nt][0] + bzv.x), gv0.y * (acc[nt][1] + bzv.y));
            *(float2*)(out + (pair0 + r + 8) * (size_t)CZ + c) =
                make_float2(gv1.x * (acc[nt][2] + bzv.x), gv1.y * (acc[nt][3] + bzv.y));
        }
    }
}

// ============================================================================
// kernel_launch — sequential, single stream
// ============================================================================
extern "C" void kernel_launch(void* const* d_in, const int* in_sizes, int n_in,
                              void* d_out, int out_size)
{
    const float* z        = (const float*)d_in[0];
    const float* ln_in_w  = (const float*)d_in[1];
    const float* ln_in_b  = (const float*)d_in[2];
    const float* ln_out_w = (const float*)d_in[3];
    const float* ln_out_b = (const float*)d_in[4];
    const float* w_ap     = (const float*)d_in[5];
    const float* b_ap     = (const float*)d_in[6];
    const float* w_ag     = (const float*)d_in[7];
    const float* b_ag     = (const float*)d_in[8];
    const float* w_bp     = (const float*)d_in[9];
    const float* b_bp     = (const float*)d_in[10];
    const float* w_bg     = (const float*)d_in[11];
    const float* b_bg     = (const float*)d_in[12];
    const float* w_g      = (const float*)d_in[13];
    const float* b_g      = (const float*)d_in[14];
    const float* w_z      = (const float*)d_in[15];
    const float* b_z      = (const float*)d_in[16];
    float* out = (float*)d_out;

    const int PROJ_SMEM = (128 * 132 + 64 * 132) * 4;          // 101376
    const int TRI_SMEM  = 4 * 4608 * 4;                        // 73728
    const int FIN_SMEM  = (128 * 72 + 64 * 132 + 640) * 4;     // 73216

    cudaFuncSetAttribute(proj_all_kernel, cudaFuncAttributeMaxDynamicSharedMemorySize, PROJ_SMEM);
    cudaFuncSetAttribute(tri_kernel,      cudaFuncAttributeMaxDynamicSharedMemorySize, TRI_SMEM);
    cudaFuncSetAttribute(final_kernel,    cudaFuncAttributeMaxDynamicSharedMemorySize, FIN_SMEM);

    dim3 pgrid(64, 6);
    prep_w<<<pgrid, 256>>>(w_ap, w_ag, w_bp, w_bg, w_g, w_z);

    proj_all_kernel<<<NPAIR / 128, 256, PROJ_SMEM>>>(
        z, ln_in_w, ln_in_b, b_ap, b_ag, b_bp, b_bg, b_g);

    dim3 tgrid(4, 4, 128);
    tri_kernel<<<tgrid, 256, TRI_SMEM>>>();

    final_kernel<<<NPAIR / 64, 256, FIN_SMEM>>>(ln_out_w, ln_out_b, b_z, out);
}